// round 1
// baseline (speedup 1.0000x reference)
#include <cuda_runtime.h>

// SpectralConv2d via Discrete Hartley Transform — fully fused pipeline.
//
// Shapes: x[8,32,256,256] f32, w1/w2[32,32,32,32] f32, out[8,32,256,256] f32.
//
// Derivation:
//   A[b,c,blk,x,y]   = sum_k x[b,c,row(blk,x),k] * cas(2pi*k*y/256),  y<32
//   r[b,o,blk,x,y]   = sum_i A[b,i,blk,x,y] * w_blk[i,o,x,y]
//   out[b,o,row,k]   = sum_y r[b,o,blk,x,y] * M[y,k]          (rows in blocks)
//   out[b,o,row,k]   = 0                                      (rows 32..223)
//   M[y,k] = ( sum_j cas(2pi*y*j/32) * cas(2pi*j*k/256) ) / 2^42
//   (2^42 = 262144 * 16777216, the two idht divisors of the reference)

#define NB   8
#define NC   32
#define S    256
#define MM   32

__device__ float g_B[256 * 32];              // B[k][y] = cas(2pi*k*y/256)
__device__ float g_M[32 * 256];              // folded trailing transforms
__device__ float g_A[NB * 2 * 32 * 32 * 32]; // A[b][blk][x][i][y]  (2 MB)

// ---------------------------------------------------------------------------
// K0: build cas tables and the folded matrix M. Deterministic, cheap.
// grid 32 x 256 threads; gid in [0, 8192) indexes both g_B and g_M entries.
// ---------------------------------------------------------------------------
__global__ void k0_tables() {
    __shared__ float cas256[256];
    __shared__ float cas32[32];
    const float TWO_PI = 6.283185307179586476925286766559f;
    int t = threadIdx.x;
    {
        float s, c;
        sincosf((TWO_PI / 256.0f) * (float)t, &s, &c);
        cas256[t] = c + s;
        if (t < 32) {
            float s2, c2;
            sincosf((TWO_PI / 32.0f) * (float)t, &s2, &c2);
            cas32[t] = c2 + s2;
        }
    }
    __syncthreads();
    int gid = blockIdx.x * 256 + t;          // 0..8191
    {   // B[k][y], k = gid>>5, y = gid&31; cas is periodic so reduce mod 256
        int k = gid >> 5, y = gid & 31;
        g_B[gid] = cas256[(k * y) & 255];
    }
    {   // M[y][k] = 2^-42 * sum_j cas32[(y*j)%32] * cas256[(j*k)%256]
        int y = gid >> 8, k = gid & 255;
        float acc = 0.0f;
#pragma unroll
        for (int j = 0; j < 32; j++)
            acc += cas32[(y * j) & 31] * cas256[(j * k) & 255];
        g_M[gid] = acc * 0x1p-42f;
    }
}

// ---------------------------------------------------------------------------
// K3: zero-fill the dead output rows [32, 224) for all 256 (b,o) images.
// 3,145,728 float4 stores = 50 MB. Pure bandwidth.
// ---------------------------------------------------------------------------
__global__ void k3_zero(float4* __restrict__ out4) {
    int tid = blockIdx.x * blockDim.x + threadIdx.x;
    int img = tid / 12288;                   // 192 rows * 256 cols / 4 = 12288
    int rem = tid - img * 12288;
    if (img < 256)
        out4[img * 16384 + 2048 + rem] = make_float4(0.f, 0.f, 0.f, 0.f);
}

// ---------------------------------------------------------------------------
// K1: corner-tile DHT.  One block per (b, blk, x); blockDim (32 y, 32 i).
// Each warp owns one input channel row (256 floats, held 8/lane in regs,
// broadcast via shfl); cas table in smem (conflict-free: lane y consecutive).
// ---------------------------------------------------------------------------
__global__ void k1_dht_rows(const float* __restrict__ xin) {
    __shared__ float Bs[256 * 32];
    int y = threadIdx.x;                     // lane
    int i = threadIdx.y;                     // warp = input channel
    int bid = blockIdx.x;                    // ((b*2 + blk)*32 + x)
    int x   = bid & 31;
    int blk = (bid >> 5) & 1;
    int b   = bid >> 6;
    int row = blk ? (224 + x) : x;

    int t = i * 32 + y;
    for (int n = t; n < 256 * 32; n += 1024) Bs[n] = g_B[n];

    const float* xr = xin + (((size_t)(b * NC + i)) * S + row) * S;
    float xv[8];
#pragma unroll
    for (int j = 0; j < 8; j++) xv[j] = xr[j * 32 + y];
    __syncthreads();

    float acc = 0.0f;
#pragma unroll
    for (int j = 0; j < 8; j++) {
#pragma unroll
        for (int l = 0; l < 32; l++) {
            float v = __shfl_sync(0xffffffffu, xv[j], l);
            acc += v * Bs[(j * 32 + l) * 32 + y];
        }
    }
    g_A[(size_t)bid * 1024 + i * 32 + y] = acc;
}

// ---------------------------------------------------------------------------
// K2: fused channel-mix + folded trailing transforms + output store.
// One block per (b, blk, x), 256 threads.
//   phase 1: r[o][y] = sum_i A[i][y] * w[i][o][x][y]
//            warp w handles o in {w, w+8, w+16, w+24}; lane = y (coalesced w).
//   phase 2: out[o][k] = sum_y r[o][y] * M[y][k]; thread = k (coalesced out).
// Smem: A 4KB + r 4KB + M 32KB = 40KB.
// ---------------------------------------------------------------------------
__global__ void k2_mix(const float* __restrict__ w1,
                       const float* __restrict__ w2,
                       float* __restrict__ out) {
    __shared__ float As[1024];          // [i][y]
    __shared__ float rs[1024];          // [o][y]
    __shared__ float Ms[32 * 256];      // [y][k]
    int t   = threadIdx.x;
    int bid = blockIdx.x;
    int x   = bid & 31;
    int blk = (bid >> 5) & 1;
    int b   = bid >> 6;
    int row = blk ? (224 + x) : x;
    const float* w = blk ? w2 : w1;

    for (int n = t; n < 1024; n += 256) As[n] = g_A[(size_t)bid * 1024 + n];
    for (int n = t; n < 32 * 256; n += 256) Ms[n] = g_M[n];
    __syncthreads();

    int warp = t >> 5, y = t & 31;
#pragma unroll
    for (int oo = 0; oo < 4; oo++) {
        int o = warp + oo * 8;
        // w index: ((i*32 + o)*32 + x)*32 + y
        const float* wp = w + (size_t)(o * 1024 + x * 32 + y);
        float acc = 0.0f;
#pragma unroll 8
        for (int i = 0; i < 32; i++)
            acc += As[i * 32 + y] * wp[(size_t)i * 32768];
        rs[o * 32 + y] = acc;
    }
    __syncthreads();

    int k = t;                           // 0..255
    float* op = out + ((size_t)(b * NC) * S + row) * S + k;
    for (int o = 0; o < 32; o++) {
        float acc = 0.0f;
#pragma unroll
        for (int yy = 0; yy < 32; yy++)
            acc += rs[o * 32 + yy] * Ms[yy * 256 + k];
        op[(size_t)o * S * S] = acc;
    }
}

// ---------------------------------------------------------------------------
extern "C" void kernel_launch(void* const* d_in, const int* in_sizes, int n_in,
                              void* d_out, int out_size) {
    const float* x  = (const float*)d_in[0];
    const float* w1 = (const float*)d_in[1];
    const float* w2 = (const float*)d_in[2];
    float* out = (float*)d_out;

    k0_tables<<<32, 256>>>();
    k3_zero<<<12288, 256>>>((float4*)d_out);
    k1_dht_rows<<<NB * 2 * 32, dim3(32, 32)>>>(x);
    k2_mix<<<NB * 2 * 32, 256>>>(w1, w2, out);
}

// round 3
// speedup vs baseline: 1.5172x; 1.5172x over previous
#include <cuda_runtime.h>

// SpectralConv2d via DHT — single fused compute kernel + table-builder.
//
// Shapes: x[8,32,256,256] f32, w1/w2[32,32,32,32] f32, out[8,32,256,256] f32.
//
//   A[i][y]   = sum_k x[b,i,row,k] * cas(2pi*k*y/256)        (y < 32)
//   r[o][y]   = sum_i A[i][y] * w_blk[i,o,x,y]
//   out[o][k] = sum_y r[o][y] * M[y][k]   for the 64 live rows; 0 elsewhere
//   M[y][k]   = ( sum_j cas(2pi*y*j/32) * cas(2pi*j*k/256) ) * 2^-42
//   (2^-42 folds both idht divisors: 1/2^18 and 1/2^24)

#define NB 8
#define S  256

__device__ float g_cas256[256];
__device__ float g_M[32 * 256];

// ---------------------------------------------------------------------------
// K0: build the 256-entry cas table and the folded 32x256 matrix M.
// ---------------------------------------------------------------------------
__global__ void k0_tables() {
    __shared__ float c256[256];
    __shared__ float c32[32];
    const float TWO_PI = 6.283185307179586476925286766559f;
    int t = threadIdx.x;
    {
        float s, c;
        sincosf((TWO_PI / 256.0f) * (float)t, &s, &c);
        c256[t] = c + s;
        if (t < 32) {
            float s2, c2;
            sincosf((TWO_PI / 32.0f) * (float)t, &s2, &c2);
            c32[t] = c2 + s2;
        }
    }
    __syncthreads();
    if (blockIdx.x == 0) g_cas256[t] = c256[t];
    int gid = blockIdx.x * 256 + t;          // 0..8191
    int y = gid >> 8, k = gid & 255;
    float acc = 0.0f;
#pragma unroll
    for (int j = 0; j < 32; j++)
        acc += c32[(y * j) & 31] * c256[(j * k) & 255];
    g_M[gid] = acc * 0x1p-42f;
}

// ---------------------------------------------------------------------------
// F: fused DHT + channel mix + folded inverse transforms + zero-fill.
// One block per (b, blk, x); 256 threads.
//   zero : each block zeroes half of one image's dead rows (24 STG.128/thr)
//   A    : A[i][y] = sum_k xs[k][i] * cas256[(k*y)&255]   (4 i per thread)
//   mix  : r[o][y] = sum_i A[i][y] * w[i][o][x][y]        (4 o per thread, LDG)
//   out  : out[o][k] = sum_y rst[y][o] * M[y][k]          (8o x 4k per thread)
// ---------------------------------------------------------------------------
__global__ __launch_bounds__(256) void f_fused(const float* __restrict__ xin,
                                               const float* __restrict__ w1,
                                               const float* __restrict__ w2,
                                               float* __restrict__ out) {
    __shared__ float xs[256 * 36];   // [k][i], pitch 36 (16B-aligned, low confl)
    __shared__ float cs[256];        // cas256
    __shared__ float As[32 * 33];    // [i][y], pitch 33
    __shared__ float rst[32 * 36];   // [y][o], pitch 36 (16B-aligned)

    int t   = threadIdx.x;
    int bid = blockIdx.x;
    int x   = bid & 31;
    int blk = (bid >> 5) & 1;
    int b   = bid >> 6;
    int row = blk ? (224 + x) : x;
    const float* w = blk ? w2 : w1;

    // ---- zero-fill dead rows [32,224): block covers half of one image ----
    {
        int img = bid >> 1, half = bid & 1;
        float4* o4 = (float4*)out + (size_t)img * 16384 + 2048 + half * 6144 + t;
#pragma unroll
        for (int j = 0; j < 24; j++) o4[j * 256] = make_float4(0.f, 0.f, 0.f, 0.f);
    }

    cs[t] = g_cas256[t];

    // ---- load x rows transposed into xs[k][i] ----
    const float* xb = xin + (((size_t)b * 32) * S + row) * S;
#pragma unroll
    for (int n = t; n < 2048; n += 256) {
        int i = n >> 6, k0 = (n & 63) * 4;
        float4 v = *(const float4*)(xb + (size_t)i * (S * S) + k0);
        xs[(k0 + 0) * 36 + i] = v.x;
        xs[(k0 + 1) * 36 + i] = v.y;
        xs[(k0 + 2) * 36 + i] = v.z;
        xs[(k0 + 3) * 36 + i] = v.w;
    }
    __syncthreads();

    // ---- phase A: corner DHT along last axis ----
    int y = t & 31, ig = t >> 5;
    {
        float a0 = 0.f, a1 = 0.f, a2 = 0.f, a3 = 0.f;
#pragma unroll 8
        for (int k = 0; k < 256; k++) {
            float4 xv = *(const float4*)&xs[k * 36 + 4 * ig];
            float  c  = cs[(k * y) & 255];
            a0 += xv.x * c; a1 += xv.y * c; a2 += xv.z * c; a3 += xv.w * c;
        }
        As[(4 * ig + 0) * 33 + y] = a0;
        As[(4 * ig + 1) * 33 + y] = a1;
        As[(4 * ig + 2) * 33 + y] = a2;
        As[(4 * ig + 3) * 33 + y] = a3;
    }
    __syncthreads();

    // ---- phase 1: channel mix, write transposed rst[y][o] ----
    {
        int og = t >> 5;                         // warp id
#pragma unroll
        for (int oo = 0; oo < 4; oo++) {
            int o = og + 8 * oo;
            const float* wp = w + (size_t)o * 1024 + x * 32 + y;
            float acc = 0.f;
#pragma unroll
            for (int i = 0; i < 32; i++)
                acc += As[i * 33 + y] * wp[(size_t)i * 32768];
            rst[y * 36 + o] = acc;
        }
    }
    __syncthreads();

    // ---- phase 2: trailing transforms via folded M; 8o x 4k per thread ----
    {
        int k4 = (t & 63) * 4;
        int ob = (t >> 6) * 8;
        float4 acc[8];
#pragma unroll
        for (int j = 0; j < 8; j++) acc[j] = make_float4(0.f, 0.f, 0.f, 0.f);
#pragma unroll 4
        for (int yy = 0; yy < 32; yy++) {
            float4 m4 = *(const float4*)&g_M[yy * 256 + k4];
            float4 r0 = *(const float4*)&rst[yy * 36 + ob];
            float4 r1 = *(const float4*)&rst[yy * 36 + ob + 4];
            float rv[8] = {r0.x, r0.y, r0.z, r0.w, r1.x, r1.y, r1.z, r1.w};
#pragma unroll
            for (int j = 0; j < 8; j++) {
                acc[j].x += rv[j] * m4.x;
                acc[j].y += rv[j] * m4.y;
                acc[j].z += rv[j] * m4.z;
                acc[j].w += rv[j] * m4.w;
            }
        }
        float* op = out + (((size_t)(b * 32 + ob)) * S + row) * S + k4;
#pragma unroll
        for (int j = 0; j < 8; j++)
            *(float4*)(op + (size_t)j * (S * S)) = acc[j];
    }
}

// ---------------------------------------------------------------------------
extern "C" void kernel_launch(void* const* d_in, const int* in_sizes, int n_in,
                              void* d_out, int out_size) {
    const float* x  = (const float*)d_in[0];
    const float* w1 = (const float*)d_in[1];
    const float* w2 = (const float*)d_in[2];
    float* out = (float*)d_out;

    k0_tables<<<32, 256>>>();
    f_fused<<<NB * 2 * 32, 256>>>(x, w1, w2, out);
}

// round 6
// speedup vs baseline: 1.9000x; 1.2523x over previous
#include <cuda_runtime.h>

// SpectralConv2d via DHT — fused kernel, conflict-free smem layouts.
// (No inline-asm f32x2: suspected toolchain issue on sm_100a; scalar FFMA.)
//
//   A[i][y]   = sum_k x[b,i,row,k] * B[k][y],   B[k][y]=cas(2pi*k*y/256), y<32
//   r[o][y]   = sum_i A[i][y] * w_blk[i,o,x,y]
//   out[o][k] = sum_y r[o][y] * M[y][k]   for the 64 live rows; 0 elsewhere
//   M[y][k]   = ( sum_j cas(2pi*y*j/32) * cas(2pi*j*k/256) ) * 2^-42

#define NB 8
#define S  256

__device__ float4 g_Bt[64 * 32];   // [kc][y] = {B[4kc][y]..B[4kc+3][y]}
__device__ float  g_M[32 * 256];   // folded trailing transforms

// ---------------------------------------------------------------------------
// K0: build g_Bt and the folded 32x256 matrix M.
// ---------------------------------------------------------------------------
__global__ void k0_tables() {
    __shared__ float c256[256];
    __shared__ float c32[32];
    const float TWO_PI = 6.283185307179586476925286766559f;
    int t = threadIdx.x;
    {
        float s, c;
        sincosf((TWO_PI / 256.0f) * (float)t, &s, &c);
        c256[t] = c + s;
        if (t < 32) {
            float s2, c2;
            sincosf((TWO_PI / 32.0f) * (float)t, &s2, &c2);
            c32[t] = c2 + s2;
        }
    }
    __syncthreads();
    int gid = blockIdx.x * 256 + t;          // 0..8191
    {   // M[y][k]
        int y = gid >> 8, k = gid & 255;
        float acc = 0.0f;
#pragma unroll
        for (int j = 0; j < 32; j++)
            acc += c32[(y * j) & 31] * c256[(j * k) & 255];
        g_M[gid] = acc * 0x1p-42f;
    }
    if (gid < 2048) {                        // g_Bt[kc][y]
        int kc = gid >> 5, y = gid & 31;
        float4 v;
        v.x = c256[((4 * kc + 0) * y) & 255];
        v.y = c256[((4 * kc + 1) * y) & 255];
        v.z = c256[((4 * kc + 2) * y) & 255];
        v.w = c256[((4 * kc + 3) * y) & 255];
        g_Bt[gid] = v;
    }
}

// ---------------------------------------------------------------------------
// F: fused DHT + channel mix + folded inverse transforms + zero-fill.
// One block per (b, blk, x); 256 threads.
//   zero : each block zeroes half of one image's dead rows (24 STG.128/thr)
//   A    : A[i][y] = sum_k xs[i][k]*B[k][y]; x in natural layout ->
//          broadcast LDS.128 per warp; B via coalesced LDG.128 (L1-resident)
//   mix  : r[o][y] = sum_i A[i][y]*w[..]; thread=(yg,o) -> LDG.128 on w
//   out  : out[o][k] = sum_y rst[y][o]*M[y][k]; broadcast LDS + LDG.128 on M
// ---------------------------------------------------------------------------
__global__ __launch_bounds__(256) void f_fused(const float* __restrict__ xin,
                                               const float* __restrict__ w1,
                                               const float* __restrict__ w2,
                                               float* __restrict__ out) {
    __shared__ float4 xs4[32 * 64];   // [i][kc]  natural layout, 32 KB
    __shared__ float  As[32 * 36];    // [i][y]   pitch 36 (float4-aligned)
    __shared__ float  rst[32 * 33];   // [y][o]   pitch 33 (conflict-free writes)

    int t   = threadIdx.x;
    int bid = blockIdx.x;
    int x   = bid & 31;
    int blk = (bid >> 5) & 1;
    int b   = bid >> 6;
    int row = blk ? (224 + x) : x;
    const float* w = blk ? w2 : w1;

    // ---- zero-fill dead rows [32,224): each block does half of one image ----
    {
        int img = bid >> 1, half = bid & 1;
        float4* o4 = (float4*)out + (size_t)img * 16384 + 2048 + half * 6144 + t;
#pragma unroll
        for (int j = 0; j < 24; j++) o4[j * 256] = make_float4(0.f, 0.f, 0.f, 0.f);
    }

    // ---- load x rows (natural layout, coalesced, conflict-free) ----
    const float4* xb4 = (const float4*)(xin + (((size_t)b * 32) * S + row) * S);
#pragma unroll
    for (int n = t; n < 2048; n += 256) {
        int i = n >> 6, kc = n & 63;
        xs4[n] = xb4[(size_t)i * (S * S / 4) + kc];
    }
    __syncthreads();

    // ---- phase A: corner DHT. thread (y=lane, ig=warp) -> A[4ig..4ig+3][y] ----
    {
        int y = t & 31, ig = t >> 5;
        float a0 = 0.f, a1 = 0.f, a2 = 0.f, a3 = 0.f;
        const float4* Bt = g_Bt + y;
        const float4* xr = xs4 + 4 * ig * 64;
#pragma unroll 8
        for (int kc = 0; kc < 64; kc++) {
            float4 bv = __ldg(&Bt[kc * 32]);         // coalesced across lanes
            float4 x0 = xr[kc];                      // i = 4ig   (broadcast)
            float4 x1 = xr[kc + 64];                 // i = 4ig+1
            float4 x2 = xr[kc + 128];
            float4 x3 = xr[kc + 192];
            a0 += x0.x*bv.x + x0.y*bv.y + x0.z*bv.z + x0.w*bv.w;
            a1 += x1.x*bv.x + x1.y*bv.y + x1.z*bv.z + x1.w*bv.w;
            a2 += x2.x*bv.x + x2.y*bv.y + x2.z*bv.z + x2.w*bv.w;
            a3 += x3.x*bv.x + x3.y*bv.y + x3.z*bv.z + x3.w*bv.w;
        }
        As[(4 * ig + 0) * 36 + y] = a0;
        As[(4 * ig + 1) * 36 + y] = a1;
        As[(4 * ig + 2) * 36 + y] = a2;
        As[(4 * ig + 3) * 36 + y] = a3;
    }
    __syncthreads();

    // ---- phase 1: channel mix. thread (yg = t&7, o = t>>3) ----
    {
        int yg = t & 7, o = t >> 3;
        float4 acc = make_float4(0.f, 0.f, 0.f, 0.f);
        const float4* wp = (const float4*)(w + (size_t)o * 1024 + x * 32 + 4 * yg);
        const float4* ap = (const float4*)(As + 4 * yg);
#pragma unroll 8
        for (int i = 0; i < 32; i++) {
            float4 wv = __ldg(&wp[(size_t)i * 8192]);  // 32768 floats / 4
            float4 av = ap[i * 9];                     // 36 floats / 4
            acc.x += av.x * wv.x;
            acc.y += av.y * wv.y;
            acc.z += av.z * wv.z;
            acc.w += av.w * wv.w;
        }
        rst[(4 * yg + 0) * 33 + o] = acc.x;
        rst[(4 * yg + 1) * 33 + o] = acc.y;
        rst[(4 * yg + 2) * 33 + o] = acc.z;
        rst[(4 * yg + 3) * 33 + o] = acc.w;
    }
    __syncthreads();

    // ---- phase 2: trailing transforms. thread (k4 = (t&63)*4, ob = (t>>6)*8) ----
    {
        int k4 = (t & 63) * 4;
        int ob = (t >> 6) * 8;
        float4 acc[8];
#pragma unroll
        for (int j = 0; j < 8; j++) acc[j] = make_float4(0.f, 0.f, 0.f, 0.f);
        const float4* Mp = (const float4*)(g_M + k4);
#pragma unroll 4
        for (int yy = 0; yy < 32; yy++) {
            float4 mv = __ldg(&Mp[yy * 64]);         // coalesced, L1-resident
            const float* rp = rst + yy * 33 + ob;
#pragma unroll
            for (int j = 0; j < 8; j++) {
                float rv = rp[j];                    // broadcast LDS
                acc[j].x += rv * mv.x;
                acc[j].y += rv * mv.y;
                acc[j].z += rv * mv.z;
                acc[j].w += rv * mv.w;
            }
        }
        float* op = out + (((size_t)(b * 32 + ob)) * S + row) * S + k4;
#pragma unroll
        for (int j = 0; j < 8; j++)
            *(float4*)(op + (size_t)j * (S * S)) = acc[j];
    }
}

// ---------------------------------------------------------------------------
extern "C" void kernel_launch(void* const* d_in, const int* in_sizes, int n_in,
                              void* d_out, int out_size) {
    const float* x  = (const float*)d_in[0];
    const float* w1 = (const float*)d_in[1];
    const float* w2 = (const float*)d_in[2];
    float* out = (float*)d_out;

    k0_tables<<<32, 256>>>();
    f_fused<<<NB * 2 * 32, 256>>>(x, w1, w2, out);
}